// round 3
// baseline (speedup 1.0000x reference)
#include <cuda_runtime.h>
#include <cstdint>
#include <cstddef>

// ---------------- problem constants ----------------
#define T_    4
#define B_    8
#define NSEQ  1024
#define C_    768
#define HD_   3072
#define H_    8
#define D_    96
#define W_    8
#define NW_   (NSEQ / W_)           // 128
#define BN_TOK (B_ * NSEQ)          // 8192
#define M_TOT (T_ * BN_TOK)         // 32768
#define PLANE_C ((size_t)BN_TOK * C_)   // 6291456
#define PLANE_H ((size_t)BN_TOK * HD_)  // 25165824

// ---------------- device scratch (no allocs allowed) ----------------
__device__ float g_buf1[(size_t)M_TOT * HD_];      // pre-activations (max width Hd); h-spikes in place
__device__ float g_spk [(size_t)M_TOT * C_ * 3];   // q,k,v spikes
__device__ float g_obuf[(size_t)M_TOT * C_];       // attention out / f2 pre
__device__ float g_x1  [(size_t)M_TOT * C_];       // residual after proj

// ---------------- fused GEMM + BN affine ----------------
// Y[m,n] = (sum_k A[m,k]*W[n,k] + bias[n]) * scale[n] + shift[n]
// M = M_TOT (divisible by 128); N divisible by 128; K divisible by 16.
__global__ __launch_bounds__(256, 2)
void gemm_bn(const float* __restrict__ A, const float* __restrict__ Wt,
             const float* __restrict__ bia, const float* __restrict__ sca,
             const float* __restrict__ shf, float* __restrict__ Y,
             int N, int K)
{
    __shared__ float As[16][128];
    __shared__ float Bs[16][128];

    const int bm = blockIdx.y * 128;
    const int bn = blockIdx.x * 128;
    const int tid = threadIdx.x;
    const int tr = tid >> 4;   // 0..15
    const int tc = tid & 15;   // 0..15

    float acc[8][8];
    #pragma unroll
    for (int i = 0; i < 8; i++)
        #pragma unroll
        for (int j = 0; j < 8; j++) acc[i][j] = 0.f;

    const float* Aptr = A + (size_t)bm * K;
    const float* Wptr = Wt + (size_t)bn * K;

    for (int k0 = 0; k0 < K; k0 += 16) {
        #pragma unroll
        for (int u = 0; u < 2; u++) {
            int L   = tid + 256 * u;     // 0..511
            int row = L >> 2;            // 0..127
            int f4  = (L & 3) << 2;      // 0,4,8,12
            float4 va = *(const float4*)(Aptr + (size_t)row * K + k0 + f4);
            As[f4 + 0][row] = va.x; As[f4 + 1][row] = va.y;
            As[f4 + 2][row] = va.z; As[f4 + 3][row] = va.w;
            float4 vb = *(const float4*)(Wptr + (size_t)row * K + k0 + f4);
            Bs[f4 + 0][row] = vb.x; Bs[f4 + 1][row] = vb.y;
            Bs[f4 + 2][row] = vb.z; Bs[f4 + 3][row] = vb.w;
        }
        __syncthreads();
        #pragma unroll
        for (int kk = 0; kk < 16; kk++) {
            float a[8], b[8];
            *(float4*)&a[0] = *(const float4*)&As[kk][tr * 8];
            *(float4*)&a[4] = *(const float4*)&As[kk][tr * 8 + 4];
            *(float4*)&b[0] = *(const float4*)&Bs[kk][tc * 8];
            *(float4*)&b[4] = *(const float4*)&Bs[kk][tc * 8 + 4];
            #pragma unroll
            for (int i = 0; i < 8; i++)
                #pragma unroll
                for (int j = 0; j < 8; j++)
                    acc[i][j] += a[i] * b[j];
        }
        __syncthreads();
    }

    float sc[8], bb[8], sh[8];
    #pragma unroll
    for (int j = 0; j < 8; j++) {
        int col = bn + tc * 8 + j;
        sc[j] = sca[col]; bb[j] = bia[col]; sh[j] = shf[col];
    }
    #pragma unroll
    for (int i = 0; i < 8; i++) {
        int row = bm + tr * 8 + i;
        float* Yr = Y + (size_t)row * N + bn + tc * 8;
        #pragma unroll
        for (int j = 0; j < 8; j++)
            Yr[j] = (acc[i][j] + bb[j]) * sc[j] + sh[j];
    }
}

// ---------------- LIF over T (tau=2, hard reset) ----------------
// v = v + (x - v)/2; s = (v >= vth); v = s ? 0 : v
// Safe in-place (spk == pre): each thread reads pre[t][idx] before writing spk[t][idx].
__global__ void lif_kernel(const float4* __restrict__ pre, float4* __restrict__ spk,
                           size_t plane4, float vth)
{
    size_t idx = (size_t)blockIdx.x * blockDim.x + threadIdx.x;
    if (idx >= plane4) return;
    float vx = 0.f, vy = 0.f, vz = 0.f, vw = 0.f;
    #pragma unroll
    for (int t = 0; t < T_; t++) {
        float4 xv = pre[(size_t)t * plane4 + idx];
        float4 s;
        vx = vx + (xv.x - vx) * 0.5f; s.x = (vx >= vth) ? 1.f : 0.f; if (s.x != 0.f) vx = 0.f;
        vy = vy + (xv.y - vy) * 0.5f; s.y = (vy >= vth) ? 1.f : 0.f; if (s.y != 0.f) vy = 0.f;
        vz = vz + (xv.z - vz) * 0.5f; s.z = (vz >= vth) ? 1.f : 0.f; if (s.z != 0.f) vz = 0.f;
        vw = vw + (xv.w - vw) * 0.5f; s.w = (vw >= vth) ? 1.f : 0.f; if (s.w != 0.f) vw = 0.f;
        spk[(size_t)t * plane4 + idx] = s;
    }
}

// same, but out[t] = res[t] + spike (residual fusion)
__global__ void lif_add_kernel(const float4* __restrict__ pre, const float4* __restrict__ res,
                               float4* __restrict__ out, size_t plane4, float vth)
{
    size_t idx = (size_t)blockIdx.x * blockDim.x + threadIdx.x;
    if (idx >= plane4) return;
    float vx = 0.f, vy = 0.f, vz = 0.f, vw = 0.f;
    #pragma unroll
    for (int t = 0; t < T_; t++) {
        float4 xv = pre[(size_t)t * plane4 + idx];
        float4 rv = res[(size_t)t * plane4 + idx];
        float4 o;
        vx = vx + (xv.x - vx) * 0.5f; o.x = rv.x + ((vx >= vth) ? 1.f : 0.f); if (vx >= vth) vx = 0.f;
        vy = vy + (xv.y - vy) * 0.5f; o.y = rv.y + ((vy >= vth) ? 1.f : 0.f); if (vy >= vth) vy = 0.f;
        vz = vz + (xv.z - vz) * 0.5f; o.z = rv.z + ((vz >= vth) ? 1.f : 0.f); if (vz >= vth) vz = 0.f;
        vw = vw + (xv.w - vw) * 0.5f; o.w = rv.w + ((vw >= vth) ? 1.f : 0.f); if (vw >= vth) vw = 0.f;
        out[(size_t)t * plane4 + idx] = o;
    }
}

// ---------------- local windowed attention ----------------
// grid (NW_, B_, T_), 128 threads. Loops all H_ heads.
// q,k,v spike tensors laid out (T,B,N,C) with c = h*D + d.
// window w=8, look_backward=1 -> 16 keys; first window's lookback masked.
__global__ void attn_kernel(const float* __restrict__ qg, const float* __restrict__ kg,
                            const float* __restrict__ vg, float* __restrict__ og)
{
    __shared__ float Qs[8][97];
    __shared__ float Ks[16][97];
    __shared__ float Vs[16][97];
    __shared__ float At[8][16];

    const int nwi = blockIdx.x;
    const int b   = blockIdx.y;
    const int t   = blockIdx.z;
    const int tid = threadIdx.x;
    const size_t base = ((size_t)t * B_ + b) * (size_t)NSEQ * C_;
    const int n0 = nwi * W_;
    const float scale = 0.10206207261596577f; // 96^-0.5

    for (int h = 0; h < H_; h++) {
        const int c0 = h * D_;
        for (int r = tid; r < 8 * 96; r += 128) {
            int i = r / 96, d = r - i * 96;
            Qs[i][d] = qg[base + (size_t)(n0 + i) * C_ + c0 + d];
        }
        for (int r = tid; r < 16 * 96; r += 128) {
            int j = r / 96, d = r - j * 96;
            int n = n0 - 8 + j;
            float kv = 0.f, vv = 0.f;
            if (n >= 0) {
                size_t off = base + (size_t)n * C_ + c0 + d;
                kv = kg[off]; vv = vg[off];
            }
            Ks[j][d] = kv; Vs[j][d] = vv;
        }
        __syncthreads();

        const int i = tid >> 4, j = tid & 15;
        float acc = 0.f;
        #pragma unroll
        for (int d = 0; d < 96; d++) acc += Qs[i][d] * Ks[j][d];
        float sim = acc * scale;
        if (nwi == 0 && j < 8) sim = -3.0e38f;

        float mx = sim;
        #pragma unroll
        for (int off = 8; off > 0; off >>= 1)
            mx = fmaxf(mx, __shfl_xor_sync(0xffffffffu, mx, off));
        float e = expf(sim - mx);
        float ssum = e;
        #pragma unroll
        for (int off = 8; off > 0; off >>= 1)
            ssum += __shfl_xor_sync(0xffffffffu, ssum, off);
        At[i][j] = e / ssum;
        __syncthreads();

        for (int r = tid; r < 8 * 96; r += 128) {
            int ii = r / 96, d = r - ii * 96;
            float o = 0.f;
            #pragma unroll
            for (int jj = 0; jj < 16; jj++) o += At[ii][jj] * Vs[jj][d];
            og[base + (size_t)(n0 + ii) * C_ + c0 + d] = o;
        }
        __syncthreads();
    }
}

// ---------------- launch ----------------
extern "C" void kernel_launch(void* const* d_in, const int* in_sizes, int n_in,
                              void* d_out, int out_size)
{
    const float* x   = (const float*)d_in[0];
    const float* qw  = (const float*)d_in[1];
    const float* qb  = (const float*)d_in[2];
    const float* qs  = (const float*)d_in[3];
    const float* qt  = (const float*)d_in[4];
    const float* kw  = (const float*)d_in[5];
    const float* kb  = (const float*)d_in[6];
    const float* ks  = (const float*)d_in[7];
    const float* kt  = (const float*)d_in[8];
    const float* vw  = (const float*)d_in[9];
    const float* vb  = (const float*)d_in[10];
    const float* vs  = (const float*)d_in[11];
    const float* vt  = (const float*)d_in[12];
    const float* pw  = (const float*)d_in[13];
    const float* pb  = (const float*)d_in[14];
    const float* ps  = (const float*)d_in[15];
    const float* pt  = (const float*)d_in[16];
    const float* f1w = (const float*)d_in[17];
    const float* f1b = (const float*)d_in[18];
    const float* f1s = (const float*)d_in[19];
    const float* f1t = (const float*)d_in[20];
    const float* f2w = (const float*)d_in[21];
    const float* f2b = (const float*)d_in[22];
    const float* f2s = (const float*)d_in[23];
    const float* f2t = (const float*)d_in[24];

    float *buf1, *spk, *obuf, *x1b;
    cudaGetSymbolAddress((void**)&buf1, g_buf1);
    cudaGetSymbolAddress((void**)&spk,  g_spk);
    cudaGetSymbolAddress((void**)&obuf, g_obuf);
    cudaGetSymbolAddress((void**)&x1b,  g_x1);

    const size_t MC = (size_t)M_TOT * C_;
    const dim3 blk(256);
    const dim3 g768(C_ / 128, M_TOT / 128);    // (6, 256)
    const dim3 g3072(HD_ / 128, M_TOT / 128);  // (24, 256)
    const int lifBlocksC = (int)((PLANE_C / 4 + 255) / 256);
    const int lifBlocksH = (int)((PLANE_H / 4 + 255) / 256);

    // q,k,v: GEMM + BN, then LIF -> spikes
    const float* Ws[3] = {qw, kw, vw};
    const float* Bs[3] = {qb, kb, vb};
    const float* Ss[3] = {qs, ks, vs};
    const float* Ts[3] = {qt, kt, vt};
    for (int l = 0; l < 3; l++)
        gemm_bn<<<g768, blk>>>(x, Ws[l], Bs[l], Ss[l], Ts[l], buf1 + (size_t)l * MC, C_, C_);
    for (int l = 0; l < 3; l++)
        lif_kernel<<<lifBlocksC, 256>>>((const float4*)(buf1 + (size_t)l * MC),
                                        (float4*)(spk + (size_t)l * MC), PLANE_C / 4, 1.0f);

    // local attention on spikes
    attn_kernel<<<dim3(NW_, B_, T_), 128>>>(spk, spk + MC, spk + 2 * MC, obuf);

    // attn_lif (vth=0.5), in-place
    lif_kernel<<<lifBlocksC, 256>>>((const float4*)obuf, (float4*)obuf, PLANE_C / 4, 0.5f);

    // proj GEMM + BN, LIF with residual: x1 = x + spikes
    gemm_bn<<<g768, blk>>>(obuf, pw, pb, ps, pt, buf1, C_, C_);
    lif_add_kernel<<<lifBlocksC, 256>>>((const float4*)buf1, (const float4*)x,
                                        (float4*)x1b, PLANE_C / 4, 1.0f);

    // f1 GEMM + BN, LIF -> h spikes (in place in buf1)
    gemm_bn<<<g3072, blk>>>(x1b, f1w, f1b, f1s, f1t, buf1, HD_, C_);
    lif_kernel<<<lifBlocksH, 256>>>((const float4*)buf1, (float4*)buf1, PLANE_H / 4, 1.0f);

    // f2 GEMM + BN, LIF with residual: out = x1 + spikes
    gemm_bn<<<g768, blk>>>(buf1, f2w, f2b, f2s, f2t, obuf, C_, HD_);
    lif_add_kernel<<<lifBlocksC, 256>>>((const float4*)obuf, (const float4*)x1b,
                                        (float4*)d_out, PLANE_C / 4, 1.0f);
}

// round 5
// speedup vs baseline: 2.1126x; 2.1126x over previous
#include <cuda_runtime.h>
#include <cuda_bf16.h>
#include <cstdint>
#include <cstddef>

typedef __nv_bfloat16 bf16;
typedef __nv_bfloat162 bf162;

#define T_    4
#define B_    8
#define NSEQ  1024
#define C_    768
#define HD_   3072
#define H_    8
#define D_    96
#define W_    8
#define NW_   (NSEQ / W_)
#define BN_TOK (B_ * NSEQ)
#define M_TOT (T_ * BN_TOK)
#define PLANE_C ((size_t)BN_TOK * C_)
#define PLANE_H ((size_t)BN_TOK * HD_)
#define MC ((size_t)M_TOT * C_)
#define MH ((size_t)M_TOT * HD_)

#define WOFF_Q  0
#define WOFF_K  589824
#define WOFF_V  1179648
#define WOFF_P  1769472
#define WOFF_F1 2359296
#define WOFF_F2 4718592
#define WTOT    7077888

__device__ float g_pre[MH];
__device__ bf16  g_xs [3 * MC];
__device__ bf16  g_ws [3 * WTOT];
__device__ bf16  g_spk[3 * MC];
__device__ bf16  g_aspk[MC];
__device__ bf16  g_hspk[MH];
__device__ bf16  g_x1s[3 * MC];
__device__ float g_obuf[MC];
__device__ float g_x1 [MC];

__device__ __forceinline__ uint32_t smem_u32(const void* p) {
    uint32_t a;
    asm("{ .reg .u64 t; cvta.to.shared.u64 t, %1; cvt.u32.u64 %0, t; }" : "=r"(a) : "l"(p));
    return a;
}
#define SWZ(o) ((o) ^ (((o) >> 3) & 0x70))

__device__ __forceinline__ void cp16(uint32_t dst, const void* src) {
    asm volatile("cp.async.cg.shared.global [%0], [%1], 16;" :: "r"(dst), "l"(src));
}
__device__ __forceinline__ void ldmA(uint32_t* a, uint32_t addr) {
    asm volatile("ldmatrix.sync.aligned.m8n8.x4.shared.b16 {%0,%1,%2,%3}, [%4];"
                 : "=r"(a[0]), "=r"(a[1]), "=r"(a[2]), "=r"(a[3]) : "r"(addr));
}
__device__ __forceinline__ void ldmB(uint32_t* b, uint32_t addr) {
    asm volatile("ldmatrix.sync.aligned.m8n8.x2.shared.b16 {%0,%1}, [%2];"
                 : "=r"(b[0]), "=r"(b[1]) : "r"(addr));
}
__device__ __forceinline__ void mma16816(float* c, const uint32_t* a, const uint32_t* b) {
    asm volatile(
        "mma.sync.aligned.m16n8k16.row.col.f32.bf16.bf16.f32 "
        "{%0,%1,%2,%3}, {%4,%5,%6,%7}, {%8,%9}, {%0,%1,%2,%3};"
        : "+f"(c[0]), "+f"(c[1]), "+f"(c[2]), "+f"(c[3])
        : "r"(a[0]), "r"(a[1]), "r"(a[2]), "r"(a[3]), "r"(b[0]), "r"(b[1]));
}

// split-precision bf16 HMMA GEMM + BN: Y = (sum_passes A_ai @ B_bi^T + bias)*scale + shift
// Block 128x128, BK=64, double-buffered cp.async. 8 warps = 2x4, warp tile 64x32.
template <int NA>
__global__ __launch_bounds__(256, 1)
void gemm_mma(const bf16* __restrict__ A0, const bf16* __restrict__ A1, const bf16* __restrict__ A2,
              const bf16* __restrict__ B0, const bf16* __restrict__ B1, const bf16* __restrict__ B2,
              const float* __restrict__ bia, const float* __restrict__ sca,
              const float* __restrict__ shf, float* __restrict__ Y, int N, int K)
{
    extern __shared__ char smem[];
    const uint32_t sb = smem_u32(smem);
    const uint32_t tiles = (sb + 1023u) & ~1023u;
    constexpr int NT = NA + 3;
    constexpr uint32_t STAGE = NT * 16384u;

    const int bm = blockIdx.y * 128;
    const int bn = blockIdx.x * 128;
    const int tid = threadIdx.x;
    const int wid = tid >> 5, lane = tid & 31;
    const int wm0 = (wid >> 2) * 64;     // 0 or 64
    const int wn0 = (wid & 3) * 32;      // 0,32,64,96

    float acc[4][4][4];
    #pragma unroll
    for (int i = 0; i < 4; i++)
        #pragma unroll
        for (int j = 0; j < 4; j++)
            #pragma unroll
            for (int e = 0; e < 4; e++) acc[i][j][e] = 0.f;

    const bf16* Aps[3] = {A0, A1, A2};
    const bf16* Bps[3] = {B0, B1, B2};
    const int NC = K >> 6;

    auto issue_loads = [&](int chunk) {
        const uint32_t base = tiles + (uint32_t)(chunk & 1) * STAGE;
        const int k0 = chunk << 6;
        #pragma unroll
        for (int a = 0; a < NA; a++) {
            const bf16* src = Aps[a] + (size_t)bm * K + k0;
            const uint32_t tb = base + a * 16384u;
            #pragma unroll
            for (int j = 0; j < 4; j++) {
                int idx = tid + j * 256;
                int row = idx >> 3, c = idx & 7;
                cp16(tb + SWZ((uint32_t)(row * 128 + c * 16)), src + (size_t)row * K + c * 8);
            }
        }
        #pragma unroll
        for (int b = 0; b < 3; b++) {
            const bf16* src = Bps[b] + (size_t)bn * K + k0;
            const uint32_t tb = base + (NA + b) * 16384u;
            #pragma unroll
            for (int j = 0; j < 4; j++) {
                int idx = tid + j * 256;
                int row = idx >> 3, c = idx & 7;
                cp16(tb + SWZ((uint32_t)(row * 128 + c * 16)), src + (size_t)row * K + c * 8);
            }
        }
        asm volatile("cp.async.commit_group;" ::: "memory");
    };

    issue_loads(0);
    if (NC > 1) issue_loads(1);

    // ldmatrix per-lane offsets (within a tile)
    const int arow = lane & 15, akg = lane >> 4;        // A: rows m, k-halves
    const int brow = lane & 7,  bkg = (lane >> 3) & 1;  // B: rows n, k-halves

    for (int i = 0; i < NC; i++) {
        if (i < NC - 2) { asm volatile("cp.async.wait_group 1;" ::: "memory"); }
        else            { asm volatile("cp.async.wait_group 0;" ::: "memory"); }
        __syncthreads();
        const uint32_t base = tiles + (uint32_t)(i & 1) * STAGE;

        #pragma unroll
        for (int s = 0; s < 4; s++) {   // k-steps of 16 within BK=64
            const int kb = s * 32;      // byte offset of k-step
            #pragma unroll
            for (int ai = 0; ai < NA; ai++) {
                const uint32_t Ab = base + ai * 16384u;
                uint32_t af[4][4];
                #pragma unroll
                for (int ma = 0; ma < 4; ma++)
                    ldmA(af[ma], Ab + SWZ((uint32_t)((wm0 + ma * 16 + arow) * 128 + kb + akg * 16)));
                const int NB = (NA == 3) ? (3 - ai) : 3;
                #pragma unroll
                for (int bi = 0; bi < 3; bi++) {
                    if (bi >= NB) break;
                    const uint32_t Bb = base + (NA + bi) * 16384u;
                    uint32_t bf[4][2];
                    #pragma unroll
                    for (int na = 0; na < 4; na++)
                        ldmB(bf[na], Bb + SWZ((uint32_t)((wn0 + na * 8 + brow) * 128 + kb + bkg * 16)));
                    #pragma unroll
                    for (int ma = 0; ma < 4; ma++)
                        #pragma unroll
                        for (int na = 0; na < 4; na++)
                            mma16816(acc[ma][na], af[ma], bf[na]);
                }
            }
        }
        __syncthreads();
        if (i + 2 < NC) issue_loads(i + 2);
    }

    // epilogue: accum -> smem (BN applied on coalesced pass) -> global
    float* Dsm = reinterpret_cast<float*>(smem + (tiles - sb));
    const int crow = lane >> 2, ccol = (lane & 3) * 2;
    #pragma unroll
    for (int ma = 0; ma < 4; ma++)
        #pragma unroll
        for (int na = 0; na < 4; na++) {
            const int r = wm0 + ma * 16 + crow;
            const int c = wn0 + na * 8 + ccol;
            Dsm[r * 132 + c]           = acc[ma][na][0];
            Dsm[r * 132 + c + 1]       = acc[ma][na][1];
            Dsm[(r + 8) * 132 + c]     = acc[ma][na][2];
            Dsm[(r + 8) * 132 + c + 1] = acc[ma][na][3];
        }
    __syncthreads();
    for (int e = tid; e < 128 * 128; e += 256) {
        const int r = e >> 7, c = e & 127;
        const int col = bn + c;
        float v = Dsm[r * 132 + c];
        Y[(size_t)(bm + r) * N + col] = (v + bia[col]) * sca[col] + shf[col];
    }
}

__device__ __forceinline__ void split3f(float x, bf16& h1, bf16& h2, bf16& h3) {
    h1 = __float2bfloat16(x);
    float r = x - __bfloat162float(h1);
    h2 = __float2bfloat16(r);
    h3 = __float2bfloat16(r - __bfloat162float(h2));
}

__global__ void split3_kernel(const float2* __restrict__ src, bf162* __restrict__ a,
                              bf162* __restrict__ b, bf162* __restrict__ c, size_t n2)
{
    size_t i = (size_t)blockIdx.x * blockDim.x + threadIdx.x;
    if (i >= n2) return;
    float2 x = src[i];
    bf16 a0, b0, c0, a1, b1, c1;
    split3f(x.x, a0, b0, c0);
    split3f(x.y, a1, b1, c1);
    a[i] = __halves2bfloat162(a0, a1);
    b[i] = __halves2bfloat162(b0, b1);
    c[i] = __halves2bfloat162(c0, c1);
}

__global__ void lif_spk_kernel(const float2* __restrict__ pre, bf162* __restrict__ spk,
                               size_t plane2, float vth)
{
    size_t i = (size_t)blockIdx.x * blockDim.x + threadIdx.x;
    if (i >= plane2) return;
    float v0 = 0.f, v1 = 0.f;
    const bf16 one = __float2bfloat16(1.0f), zero = __float2bfloat16(0.0f);
    #pragma unroll
    for (int t = 0; t < T_; t++) {
        float2 x = pre[(size_t)t * plane2 + i];
        v0 = v0 + (x.x - v0) * 0.5f; bool s0 = (v0 >= vth); if (s0) v0 = 0.f;
        v1 = v1 + (x.y - v1) * 0.5f; bool s1 = (v1 >= vth); if (s1) v1 = 0.f;
        spk[(size_t)t * plane2 + i] = __halves2bfloat162(s0 ? one : zero, s1 ? one : zero);
    }
}

__global__ void lif_add_split_kernel(const float2* __restrict__ pre, const float2* __restrict__ res,
                                     float2* __restrict__ x1, bf162* __restrict__ s0p,
                                     bf162* __restrict__ s1p, bf162* __restrict__ s2p, size_t plane2)
{
    size_t i = (size_t)blockIdx.x * blockDim.x + threadIdx.x;
    if (i >= plane2) return;
    float v0 = 0.f, v1 = 0.f;
    #pragma unroll
    for (int t = 0; t < T_; t++) {
        float2 x = pre[(size_t)t * plane2 + i];
        float2 r = res[(size_t)t * plane2 + i];
        v0 = v0 + (x.x - v0) * 0.5f; bool sA = (v0 >= 1.f); float o0 = r.x + (sA ? 1.f : 0.f); if (sA) v0 = 0.f;
        v1 = v1 + (x.y - v1) * 0.5f; bool sB = (v1 >= 1.f); float o1 = r.y + (sB ? 1.f : 0.f); if (sB) v1 = 0.f;
        float2 o; o.x = o0; o.y = o1;
        x1[(size_t)t * plane2 + i] = o;
        bf16 a0, b0, c0, a1, b1, c1;
        split3f(o0, a0, b0, c0);
        split3f(o1, a1, b1, c1);
        s0p[(size_t)t * plane2 + i] = __halves2bfloat162(a0, a1);
        s1p[(size_t)t * plane2 + i] = __halves2bfloat162(b0, b1);
        s2p[(size_t)t * plane2 + i] = __halves2bfloat162(c0, c1);
    }
}

__global__ void lif_add_kernel(const float2* __restrict__ pre, const float2* __restrict__ res,
                               float2* __restrict__ out, size_t plane2)
{
    size_t i = (size_t)blockIdx.x * blockDim.x + threadIdx.x;
    if (i >= plane2) return;
    float v0 = 0.f, v1 = 0.f;
    #pragma unroll
    for (int t = 0; t < T_; t++) {
        float2 x = pre[(size_t)t * plane2 + i];
        float2 r = res[(size_t)t * plane2 + i];
        v0 = v0 + (x.x - v0) * 0.5f; bool sA = (v0 >= 1.f); if (sA) v0 = 0.f;
        v1 = v1 + (x.y - v1) * 0.5f; bool sB = (v1 >= 1.f); if (sB) v1 = 0.f;
        float2 o; o.x = r.x + (sA ? 1.f : 0.f); o.y = r.y + (sB ? 1.f : 0.f);
        out[(size_t)t * plane2 + i] = o;
    }
}

__global__ void attn_kernel(const bf16* __restrict__ qg, const bf16* __restrict__ kg,
                            const bf16* __restrict__ vg, float* __restrict__ og)
{
    __shared__ float Qs[8][97];
    __shared__ float Ks[16][97];
    __shared__ float Vs[16][97];
    __shared__ float At[8][16];

    const int nwi = blockIdx.x, b = blockIdx.y, t = blockIdx.z;
    const int tid = threadIdx.x;
    const size_t base = ((size_t)t * B_ + b) * (size_t)NSEQ * C_;
    const int n0 = nwi * W_;
    const float scale = 0.10206207261596577f;

    for (int h = 0; h < H_; h++) {
        const int c0 = h * D_;
        for (int r = tid; r < 8 * 96; r += 128) {
            int i = r / 96, d = r - i * 96;
            Qs[i][d] = __bfloat162float(qg[base + (size_t)(n0 + i) * C_ + c0 + d]);
        }
        for (int r = tid; r < 16 * 96; r += 128) {
            int j = r / 96, d = r - j * 96;
            int n = n0 - 8 + j;
            float kv = 0.f, vv = 0.f;
            if (n >= 0) {
                size_t off = base + (size_t)n * C_ + c0 + d;
                kv = __bfloat162float(kg[off]);
                vv = __bfloat162float(vg[off]);
            }
            Ks[j][d] = kv; Vs[j][d] = vv;
        }
        __syncthreads();

        const int i = tid >> 4, j = tid & 15;
        float acc = 0.f;
        #pragma unroll
        for (int d = 0; d < 96; d++) acc += Qs[i][d] * Ks[j][d];
        float sim = acc * scale;
        if (nwi == 0 && j < 8) sim = -3.0e38f;

        float mx = sim;
        #pragma unroll
        for (int off = 8; off > 0; off >>= 1)
            mx = fmaxf(mx, __shfl_xor_sync(0xffffffffu, mx, off));
        float e = expf(sim - mx);
        float ssum = e;
        #pragma unroll
        for (int off = 8; off > 0; off >>= 1)
            ssum += __shfl_xor_sync(0xffffffffu, ssum, off);
        At[i][j] = e / ssum;
        __syncthreads();

        for (int r = tid; r < 8 * 96; r += 128) {
            int ii = r / 96, d = r - ii * 96;
            float o = 0.f;
            #pragma unroll
            for (int jj = 0; jj < 16; jj++) o += At[ii][jj] * Vs[jj][d];
            og[base + (size_t)(n0 + ii) * C_ + c0 + d] = o;
        }
        __syncthreads();
    }
}

extern "C" void kernel_launch(void* const* d_in, const int* in_sizes, int n_in,
                              void* d_out, int out_size)
{
    const float* x   = (const float*)d_in[0];
    const float* qw  = (const float*)d_in[1];
    const float* qb  = (const float*)d_in[2];
    const float* qs  = (const float*)d_in[3];
    const float* qt  = (const float*)d_in[4];
    const float* kw  = (const float*)d_in[5];
    const float* kb  = (const float*)d_in[6];
    const float* ks  = (const float*)d_in[7];
    const float* kt  = (const float*)d_in[8];
    const float* vw  = (const float*)d_in[9];
    const float* vb  = (const float*)d_in[10];
    const float* vs  = (const float*)d_in[11];
    const float* vt  = (const float*)d_in[12];
    const float* pw  = (const float*)d_in[13];
    const float* pb  = (const float*)d_in[14];
    const float* ps  = (const float*)d_in[15];
    const float* pt  = (const float*)d_in[16];
    const float* f1w = (const float*)d_in[17];
    const float* f1b = (const float*)d_in[18];
    const float* f1s = (const float*)d_in[19];
    const float* f1t = (const float*)d_in[20];
    const float* f2w = (const float*)d_in[21];
    const float* f2b = (const float*)d_in[22];
    const float* f2s = (const float*)d_in[23];
    const float* f2t = (const float*)d_in[24];

    float *pre, *obuf, *x1b;
    bf16 *xs, *ws, *spk, *aspk, *hspk, *x1s;
    cudaGetSymbolAddress((void**)&pre,  g_pre);
    cudaGetSymbolAddress((void**)&xs,   g_xs);
    cudaGetSymbolAddress((void**)&ws,   g_ws);
    cudaGetSymbolAddress((void**)&spk,  g_spk);
    cudaGetSymbolAddress((void**)&aspk, g_aspk);
    cudaGetSymbolAddress((void**)&hspk, g_hspk);
    cudaGetSymbolAddress((void**)&x1s,  g_x1s);
    cudaGetSymbolAddress((void**)&obuf, g_obuf);
    cudaGetSymbolAddress((void**)&x1b,  g_x1);

    const int SZ3 = 1024 + 2 * 6 * 16384;   // NA=3: 197632
    const int SZ1 = 1024 + 2 * 4 * 16384;   // NA=1: 132096
    cudaFuncSetAttribute(gemm_mma<3>, cudaFuncAttributeMaxDynamicSharedMemorySize, SZ3);
    cudaFuncSetAttribute(gemm_mma<1>, cudaFuncAttributeMaxDynamicSharedMemorySize, SZ1);

    {   // split x
        size_t n2 = MC / 2;
        split3_kernel<<<(int)((n2 + 255) / 256), 256>>>((const float2*)x,
            (bf162*)xs, (bf162*)(xs + MC), (bf162*)(xs + 2 * MC), n2);
    }
    const float* wsrc[6] = {qw, kw, vw, pw, f1w, f2w};
    const size_t woff[6] = {WOFF_Q, WOFF_K, WOFF_V, WOFF_P, WOFF_F1, WOFF_F2};
    const size_t wcnt[6] = {(size_t)C_ * C_, (size_t)C_ * C_, (size_t)C_ * C_,
                            (size_t)C_ * C_, (size_t)C_ * HD_, (size_t)C_ * HD_};
    for (int wI = 0; wI < 6; wI++) {
        size_t n2 = wcnt[wI] / 2;
        split3_kernel<<<(int)((n2 + 255) / 256), 256>>>((const float2*)wsrc[wI],
            (bf162*)(ws + woff[wI]), (bf162*)(ws + WTOT + woff[wI]),
            (bf162*)(ws + 2 * WTOT + woff[wI]), n2);
    }

    const int lifC = (int)((PLANE_C / 2 + 255) / 256);
    const int lifH = (int)((PLANE_H / 2 + 255) / 256);
    const dim3 gC(C_ / 128, M_TOT / 128);
    const dim3 gH(HD_ / 128, M_TOT / 128);

    // q,k,v
    const size_t wq[3] = {WOFF_Q, WOFF_K, WOFF_V};
    const float* bb[3] = {qb, kb, vb};
    const float* ss[3] = {qs, ks, vs};
    const float* tt[3] = {qt, kt, vt};
    for (int l = 0; l < 3; l++) {
        gemm_mma<3><<<gC, 256, SZ3>>>(xs, xs + MC, xs + 2 * MC,
            ws + wq[l], ws + WTOT + wq[l], ws + 2 * WTOT + wq[l],
            bb[l], ss[l], tt[l], pre, C_, C_);
        lif_spk_kernel<<<lifC, 256>>>((const float2*)pre, (bf162*)(spk + (size_t)l * MC),
                                      PLANE_C / 2, 1.0f);
    }

    // attention + attn_lif
    attn_kernel<<<dim3(NW_, B_, T_), 128>>>(spk, spk + MC, spk + 2 * MC, obuf);
    lif_spk_kernel<<<lifC, 256>>>((const float2*)obuf, (bf162*)aspk, PLANE_C / 2, 0.5f);

    // proj (spike A, 3 passes) -> x1 = x + spikes, plus x1 splits
    gemm_mma<1><<<gC, 256, SZ1>>>(aspk, aspk, aspk,
        ws + WOFF_P, ws + WTOT + WOFF_P, ws + 2 * WTOT + WOFF_P,
        pb, ps, pt, pre, C_, C_);
    lif_add_split_kernel<<<lifC, 256>>>((const float2*)pre, (const float2*)x,
        (float2*)x1b, (bf162*)x1s, (bf162*)(x1s + MC), (bf162*)(x1s + 2 * MC), PLANE_C / 2);

    // f1 (float A, 6 passes) -> h spikes
    gemm_mma<3><<<gH, 256, SZ3>>>(x1s, x1s + MC, x1s + 2 * MC,
        ws + WOFF_F1, ws + WTOT + WOFF_F1, ws + 2 * WTOT + WOFF_F1,
        f1b, f1s, f1t, pre, HD_, C_);
    lif_spk_kernel<<<lifH, 256>>>((const float2*)pre, (bf162*)hspk, PLANE_H / 2, 1.0f);

    // f2 (spike A, 3 passes) -> out = x1 + spikes
    gemm_mma<1><<<gC, 256, SZ1>>>(hspk, hspk, hspk,
        ws + WOFF_F2, ws + WTOT + WOFF_F2, ws + 2 * WTOT + WOFF_F2,
        f2b, f2s, f2t, obuf, C_, HD_);
    lif_add_kernel<<<lifC, 256>>>((const float2*)obuf, (const float2*)x1b,
                                  (float2*)d_out, PLANE_C / 2);
}

// round 6
// speedup vs baseline: 2.9424x; 1.3928x over previous
#include <cuda_runtime.h>
#include <cuda_fp16.h>
#include <cstdint>
#include <cstddef>

typedef __half fp16;

#define T_    4
#define B_    8
#define NSEQ  1024
#define C_    768
#define C3_   2304
#define HD_   3072
#define H_    8
#define D_    96
#define W_    8
#define NW_   (NSEQ / W_)
#define BN_TOK (B_ * NSEQ)
#define M_TOT (T_ * BN_TOK)
#define PLANE_C ((size_t)BN_TOK * C_)
#define PLANE_Q ((size_t)BN_TOK * C3_)
#define PLANE_H ((size_t)BN_TOK * HD_)
#define MC ((size_t)M_TOT * C_)
#define MH ((size_t)M_TOT * HD_)

#define WOFF_Q  0
#define WOFF_P  1769472
#define WOFF_F1 2359296
#define WOFF_F2 4718592
#define WTOT    7077888

__device__ float g_pre [MH];        // pre-activations (max M*3072; qkv uses M*2304)
__device__ fp16  g_xs  [2 * MC];    // x splits
__device__ fp16  g_ws  [2 * WTOT];  // weight splits
__device__ fp16  g_spkf[(size_t)M_TOT * C3_]; // fused qkv spikes [M][2304]
__device__ fp16  g_aspk[MC];
__device__ fp16  g_hspk[MH];
__device__ fp16  g_x1s [2 * MC];
__device__ float g_obuf[MC];
__device__ float g_x1  [MC];
__device__ float g_qkvp[3 * C3_];   // concat bias | scale | shift for fused qkv

__device__ __forceinline__ uint32_t smem_u32(const void* p) {
    uint32_t a;
    asm("{ .reg .u64 t; cvta.to.shared.u64 t, %1; cvt.u32.u64 %0, t; }" : "=r"(a) : "l"(p));
    return a;
}
#define SWZ(o) ((o) ^ (((o) >> 3) & 0x70))
__device__ __forceinline__ void cp16cp(uint32_t dst, const void* src) {
    asm volatile("cp.async.cg.shared.global [%0], [%1], 16;" :: "r"(dst), "l"(src));
}
__device__ __forceinline__ void ldmA(uint32_t* a, uint32_t addr) {
    asm volatile("ldmatrix.sync.aligned.m8n8.x4.shared.b16 {%0,%1,%2,%3}, [%4];"
                 : "=r"(a[0]), "=r"(a[1]), "=r"(a[2]), "=r"(a[3]) : "r"(addr));
}
__device__ __forceinline__ void ldmB4(uint32_t* r, uint32_t addr) {
    asm volatile("ldmatrix.sync.aligned.m8n8.x4.shared.b16 {%0,%1,%2,%3}, [%4];"
                 : "=r"(r[0]), "=r"(r[1]), "=r"(r[2]), "=r"(r[3]) : "r"(addr));
}
__device__ __forceinline__ void mma16816(float* c, const uint32_t* a, const uint32_t* b) {
    asm volatile(
        "mma.sync.aligned.m16n8k16.row.col.f32.f16.f16.f32 "
        "{%0,%1,%2,%3}, {%4,%5,%6,%7}, {%8,%9}, {%0,%1,%2,%3};"
        : "+f"(c[0]), "+f"(c[1]), "+f"(c[2]), "+f"(c[3])
        : "r"(a[0]), "r"(a[1]), "r"(a[2]), "r"(a[3]), "r"(b[0]), "r"(b[1]));
}

// fp16 split-precision GEMM + BN epilogue.
// A: NA split planes (2 = float activation; 1 = exact spike plane).
// B: always 2 split planes. Passes: all ai x bi.  Block 128x128, BK=64.
template <int NA, int NSTG>
__global__ __launch_bounds__(256, 1)
void gemm_mma(const fp16* __restrict__ A0, const fp16* __restrict__ A1,
              const fp16* __restrict__ B0, const fp16* __restrict__ B1,
              const float* __restrict__ bia, const float* __restrict__ sca,
              const float* __restrict__ shf, float* __restrict__ Y, int N, int K)
{
    extern __shared__ char smem[];
    const uint32_t sb = smem_u32(smem);
    const uint32_t tiles = (sb + 1023u) & ~1023u;
    constexpr int NT = NA + 2;
    constexpr uint32_t STAGE = NT * 16384u;

    const int bm = blockIdx.y * 128;
    const int bn = blockIdx.x * 128;
    const int tid = threadIdx.x;
    const int wid = tid >> 5, lane = tid & 31;
    const int wm0 = (wid >> 2) * 64;
    const int wn0 = (wid & 3) * 32;

    float acc[4][4][4];
    #pragma unroll
    for (int i = 0; i < 4; i++)
        #pragma unroll
        for (int j = 0; j < 4; j++)
            #pragma unroll
            for (int e = 0; e < 4; e++) acc[i][j][e] = 0.f;

    const fp16* Aps[2] = {A0, A1};
    const fp16* Bps[2] = {B0, B1};
    const int NC = K >> 6;

    auto issue_loads = [&](int chunk) {
        const uint32_t base = tiles + (uint32_t)(chunk % NSTG) * STAGE;
        const int k0 = chunk << 6;
        #pragma unroll
        for (int a = 0; a < NA; a++) {
            const fp16* src = Aps[a] + (size_t)bm * K + k0;
            const uint32_t tb = base + a * 16384u;
            #pragma unroll
            for (int j = 0; j < 4; j++) {
                int idx = tid + j * 256;
                int row = idx >> 3, c = idx & 7;
                cp16cp(tb + SWZ((uint32_t)(row * 128 + c * 16)), src + (size_t)row * K + c * 8);
            }
        }
        #pragma unroll
        for (int b = 0; b < 2; b++) {
            const fp16* src = Bps[b] + (size_t)bn * K + k0;
            const uint32_t tb = base + (NA + b) * 16384u;
            #pragma unroll
            for (int j = 0; j < 4; j++) {
                int idx = tid + j * 256;
                int row = idx >> 3, c = idx & 7;
                cp16cp(tb + SWZ((uint32_t)(row * 128 + c * 16)), src + (size_t)row * K + c * 8);
            }
        }
        asm volatile("cp.async.commit_group;" ::: "memory");
    };

    #pragma unroll
    for (int p = 0; p < NSTG - 1; p++)
        if (p < NC) issue_loads(p);

    const int arow = lane & 15, akg = lane >> 4;
    const int brow = lane & 7, bkh = (lane >> 3) & 1, batm = lane >> 4;

    for (int i = 0; i < NC; i++) {
        if (i + NSTG - 1 < NC) {
            issue_loads(i + NSTG - 1);
            asm volatile("cp.async.wait_group %0;" :: "n"(NSTG - 1) : "memory");
        } else {
            asm volatile("cp.async.wait_group 0;" ::: "memory");
        }
        __syncthreads();
        const uint32_t base = tiles + (uint32_t)(i % NSTG) * STAGE;

        #pragma unroll
        for (int s = 0; s < 4; s++) {
            const int kb = s * 32;
            uint32_t af[NA][4][4];
            #pragma unroll
            for (int ai = 0; ai < NA; ai++)
                #pragma unroll
                for (int ma = 0; ma < 4; ma++)
                    ldmA(af[ai][ma], base + ai * 16384u +
                         SWZ((uint32_t)((wm0 + ma * 16 + arow) * 128 + kb + akg * 16)));
            uint32_t bfr[2][4][2];
            #pragma unroll
            for (int bi = 0; bi < 2; bi++)
                #pragma unroll
                for (int pr = 0; pr < 2; pr++) {
                    uint32_t r[4];
                    ldmB4(r, base + (NA + bi) * 16384u +
                          SWZ((uint32_t)((wn0 + pr * 16 + batm * 8 + brow) * 128 + kb + bkh * 16)));
                    bfr[bi][pr * 2][0] = r[0]; bfr[bi][pr * 2][1] = r[1];
                    bfr[bi][pr * 2 + 1][0] = r[2]; bfr[bi][pr * 2 + 1][1] = r[3];
                }
            #pragma unroll
            for (int ai = 0; ai < NA; ai++)
                #pragma unroll
                for (int bi = 0; bi < 2; bi++)
                    #pragma unroll
                    for (int ma = 0; ma < 4; ma++)
                        #pragma unroll
                        for (int na = 0; na < 4; na++)
                            mma16816(acc[ma][na], af[ai][ma], bfr[bi][na]);
        }
        __syncthreads();
    }

    float* Dsm = reinterpret_cast<float*>(smem + (tiles - sb));
    const int crow = lane >> 2, ccol = (lane & 3) * 2;
    #pragma unroll
    for (int ma = 0; ma < 4; ma++)
        #pragma unroll
        for (int na = 0; na < 4; na++) {
            const int r = wm0 + ma * 16 + crow;
            const int c = wn0 + na * 8 + ccol;
            Dsm[r * 132 + c]           = acc[ma][na][0];
            Dsm[r * 132 + c + 1]       = acc[ma][na][1];
            Dsm[(r + 8) * 132 + c]     = acc[ma][na][2];
            Dsm[(r + 8) * 132 + c + 1] = acc[ma][na][3];
        }
    __syncthreads();
    for (int e = tid; e < 128 * 128; e += 256) {
        const int r = e >> 7, c = e & 127;
        const int col = bn + c;
        float v = Dsm[r * 132 + c];
        Y[(size_t)(bm + r) * N + col] = (v + bia[col]) * sca[col] + shf[col];
    }
}

__device__ __forceinline__ void split2f(float x, fp16& h1, fp16& h2) {
    h1 = __float2half_rn(x);
    h2 = __float2half_rn(x - __half2float(h1));
}

__global__ void split2_kernel(const float2* __restrict__ src, __half2* __restrict__ a,
                              __half2* __restrict__ b, size_t n2)
{
    size_t i = (size_t)blockIdx.x * blockDim.x + threadIdx.x;
    if (i >= n2) return;
    float2 x = src[i];
    fp16 a0, b0, a1, b1;
    split2f(x.x, a0, b0);
    split2f(x.y, a1, b1);
    a[i] = __halves2half2(a0, a1);
    b[i] = __halves2half2(b0, b1);
}

__global__ void concat3_kernel(const float* __restrict__ a, const float* __restrict__ b,
                               const float* __restrict__ c, float* __restrict__ dst)
{
    int i = blockIdx.x * blockDim.x + threadIdx.x;
    if (i >= C3_) return;
    dst[i] = (i < C_) ? a[i] : (i < 2 * C_) ? b[i - C_] : c[i - 2 * C_];
}

__global__ void lif_spk_kernel(const float2* __restrict__ pre, __half2* __restrict__ spk,
                               size_t plane2, float vth)
{
    size_t i = (size_t)blockIdx.x * blockDim.x + threadIdx.x;
    if (i >= plane2) return;
    float v0 = 0.f, v1 = 0.f;
    const fp16 one = __float2half_rn(1.0f), zero = __float2half_rn(0.0f);
    #pragma unroll
    for (int t = 0; t < T_; t++) {
        float2 x = pre[(size_t)t * plane2 + i];
        v0 = v0 + (x.x - v0) * 0.5f; bool s0 = (v0 >= vth); if (s0) v0 = 0.f;
        v1 = v1 + (x.y - v1) * 0.5f; bool s1 = (v1 >= vth); if (s1) v1 = 0.f;
        spk[(size_t)t * plane2 + i] = __halves2half2(s0 ? one : zero, s1 ? one : zero);
    }
}

__global__ void lif_add_split_kernel(const float2* __restrict__ pre, const float2* __restrict__ res,
                                     float2* __restrict__ x1, __half2* __restrict__ s0p,
                                     __half2* __restrict__ s1p, size_t plane2)
{
    size_t i = (size_t)blockIdx.x * blockDim.x + threadIdx.x;
    if (i >= plane2) return;
    float v0 = 0.f, v1 = 0.f;
    #pragma unroll
    for (int t = 0; t < T_; t++) {
        float2 x = pre[(size_t)t * plane2 + i];
        float2 r = res[(size_t)t * plane2 + i];
        v0 = v0 + (x.x - v0) * 0.5f; bool sA = (v0 >= 1.f); float o0 = r.x + (sA ? 1.f : 0.f); if (sA) v0 = 0.f;
        v1 = v1 + (x.y - v1) * 0.5f; bool sB = (v1 >= 1.f); float o1 = r.y + (sB ? 1.f : 0.f); if (sB) v1 = 0.f;
        float2 o; o.x = o0; o.y = o1;
        x1[(size_t)t * plane2 + i] = o;
        fp16 a0, b0, a1, b1;
        split2f(o0, a0, b0);
        split2f(o1, a1, b1);
        s0p[(size_t)t * plane2 + i] = __halves2half2(a0, a1);
        s1p[(size_t)t * plane2 + i] = __halves2half2(b0, b1);
    }
}

__global__ void lif_add_kernel(const float2* __restrict__ pre, const float2* __restrict__ res,
                               float2* __restrict__ out, size_t plane2)
{
    size_t i = (size_t)blockIdx.x * blockDim.x + threadIdx.x;
    if (i >= plane2) return;
    float v0 = 0.f, v1 = 0.f;
    #pragma unroll
    for (int t = 0; t < T_; t++) {
        float2 x = pre[(size_t)t * plane2 + i];
        float2 r = res[(size_t)t * plane2 + i];
        v0 = v0 + (x.x - v0) * 0.5f; bool sA = (v0 >= 1.f); if (sA) v0 = 0.f;
        v1 = v1 + (x.y - v1) * 0.5f; bool sB = (v1 >= 1.f); if (sB) v1 = 0.f;
        float2 o; o.x = r.x + (sA ? 1.f : 0.f); o.y = r.y + (sB ? 1.f : 0.f);
        out[(size_t)t * plane2 + i] = o;
    }
}

// local attention over fused spike tensor [T][B*N][2304]: q@0, k@768, v@1536
__global__ void attn_kernel(const fp16* __restrict__ sf, float* __restrict__ og)
{
    __shared__ float Qs[8][97];
    __shared__ float Ks[16][97];
    __shared__ float Vs[16][97];
    __shared__ float At[8][16];

    const int nwi = blockIdx.x, b = blockIdx.y, t = blockIdx.z;
    const int tid = threadIdx.x;
    const size_t basef = ((size_t)t * B_ + b) * (size_t)NSEQ * C3_;
    const size_t baseo = ((size_t)t * B_ + b) * (size_t)NSEQ * C_;
    const int n0 = nwi * W_;
    const float scale = 0.10206207261596577f;

    for (int h = 0; h < H_; h++) {
        const int c0 = h * D_;
        for (int r = tid; r < 8 * 96; r += 128) {
            int i = r / 96, d = r - i * 96;
            Qs[i][d] = __half2float(sf[basef + (size_t)(n0 + i) * C3_ + c0 + d]);
        }
        for (int r = tid; r < 16 * 96; r += 128) {
            int j = r / 96, d = r - j * 96;
            int n = n0 - 8 + j;
            float kv = 0.f, vv = 0.f;
            if (n >= 0) {
                size_t off = basef + (size_t)n * C3_ + c0 + d;
                kv = __half2float(sf[off + C_]);
                vv = __half2float(sf[off + 2 * C_]);
            }
            Ks[j][d] = kv; Vs[j][d] = vv;
        }
        __syncthreads();

        const int i = tid >> 4, j = tid & 15;
        float acc = 0.f;
        #pragma unroll
        for (int d = 0; d < 96; d++) acc += Qs[i][d] * Ks[j][d];
        float sim = acc * scale;
        if (nwi == 0 && j < 8) sim = -3.0e38f;

        float mx = sim;
        #pragma unroll
        for (int off = 8; off > 0; off >>= 1)
            mx = fmaxf(mx, __shfl_xor_sync(0xffffffffu, mx, off));
        float e = expf(sim - mx);
        float ssum = e;
        #pragma unroll
        for (int off = 8; off > 0; off >>= 1)
            ssum += __shfl_xor_sync(0xffffffffu, ssum, off);
        At[i][j] = e / ssum;
        __syncthreads();

        for (int r = tid; r < 8 * 96; r += 128) {
            int ii = r / 96, d = r - ii * 96;
            float o = 0.f;
            #pragma unroll
            for (int jj = 0; jj < 16; jj++) o += At[ii][jj] * Vs[jj][d];
            og[baseo + (size_t)(n0 + ii) * C_ + c0 + d] = o;
        }
        __syncthreads();
    }
}

extern "C" void kernel_launch(void* const* d_in, const int* in_sizes, int n_in,
                              void* d_out, int out_size)
{
    const float* x   = (const float*)d_in[0];
    const float* qw  = (const float*)d_in[1];
    const float* qb  = (const float*)d_in[2];
    const float* qs  = (const float*)d_in[3];
    const float* qt  = (const float*)d_in[4];
    const float* kw  = (const float*)d_in[5];
    const float* kb  = (const float*)d_in[6];
    const float* ks  = (const float*)d_in[7];
    const float* kt  = (const float*)d_in[8];
    const float* vw  = (const float*)d_in[9];
    const float* vb  = (const float*)d_in[10];
    const float* vs  = (const float*)d_in[11];
    const float* vt  = (const float*)d_in[12];
    const float* pw  = (const float*)d_in[13];
    const float* pb  = (const float*)d_in[14];
    const float* ps  = (const float*)d_in[15];
    const float* pt  = (const float*)d_in[16];
    const float* f1w = (const float*)d_in[17];
    const float* f1b = (const float*)d_in[18];
    const float* f1s = (const float*)d_in[19];
    const float* f1t = (const float*)d_in[20];
    const float* f2w = (const float*)d_in[21];
    const float* f2b = (const float*)d_in[22];
    const float* f2s = (const float*)d_in[23];
    const float* f2t = (const float*)d_in[24];

    float *pre, *obuf, *x1b, *qkvp;
    fp16 *xs, *ws, *spkf, *aspk, *hspk, *x1s;
    cudaGetSymbolAddress((void**)&pre,  g_pre);
    cudaGetSymbolAddress((void**)&xs,   g_xs);
    cudaGetSymbolAddress((void**)&ws,   g_ws);
    cudaGetSymbolAddress((void**)&spkf, g_spkf);
    cudaGetSymbolAddress((void**)&aspk, g_aspk);
    cudaGetSymbolAddress((void**)&hspk, g_hspk);
    cudaGetSymbolAddress((void**)&x1s,  g_x1s);
    cudaGetSymbolAddress((void**)&obuf, g_obuf);
    cudaGetSymbolAddress((void**)&x1b,  g_x1);
    cudaGetSymbolAddress((void**)&qkvp, g_qkvp);

    const int SZ2 = 1024 + 3 * 4 * 16384;   // NA=2, NSTG=3: 197632
    const int SZ1 = 1024 + 4 * 3 * 16384;   // NA=1, NSTG=4: 197632
    cudaFuncSetAttribute((gemm_mma<2, 3>), cudaFuncAttributeMaxDynamicSharedMemorySize, SZ2);
    cudaFuncSetAttribute((gemm_mma<1, 4>), cudaFuncAttributeMaxDynamicSharedMemorySize, SZ1);

    // splits
    {
        size_t n2 = MC / 2;
        split2_kernel<<<(int)((n2 + 255) / 256), 256>>>((const float2*)x,
            (__half2*)xs, (__half2*)(xs + MC), n2);
    }
    const float* wsrc[6] = {qw, kw, vw, pw, f1w, f2w};
    const size_t woff[6] = {WOFF_Q, WOFF_Q + (size_t)C_ * C_, WOFF_Q + 2 * (size_t)C_ * C_,
                            WOFF_P, WOFF_F1, WOFF_F2};
    const size_t wcnt[6] = {(size_t)C_ * C_, (size_t)C_ * C_, (size_t)C_ * C_,
                            (size_t)C_ * C_, (size_t)C_ * HD_, (size_t)C_ * HD_};
    for (int wI = 0; wI < 6; wI++) {
        size_t n2 = wcnt[wI] / 2;
        split2_kernel<<<(int)((n2 + 255) / 256), 256>>>((const float2*)wsrc[wI],
            (__half2*)(ws + woff[wI]), (__half2*)(ws + WTOT + woff[wI]), n2);
    }
    concat3_kernel<<<(C3_ + 255) / 256, 256>>>(qb, kb, vb, qkvp);
    concat3_kernel<<<(C3_ + 255) / 256, 256>>>(qs, ks, vs, qkvp + C3_);
    concat3_kernel<<<(C3_ + 255) / 256, 256>>>(qt, kt, vt, qkvp + 2 * C3_);

    const int lifC = (int)((PLANE_C / 2 + 255) / 256);
    const int lifQ = (int)((PLANE_Q / 2 + 255) / 256);
    const int lifH = (int)((PLANE_H / 2 + 255) / 256);

    // fused qkv GEMM (N=2304) + fused LIF
    gemm_mma<2, 3><<<dim3(C3_ / 128, M_TOT / 128), 256, SZ2>>>(
        xs, xs + MC, ws + WOFF_Q, ws + WTOT + WOFF_Q,
        qkvp, qkvp + C3_, qkvp + 2 * C3_, pre, C3_, C_);
    lif_spk_kernel<<<lifQ, 256>>>((const float2*)pre, (__half2*)spkf, PLANE_Q / 2, 1.0f);

    // attention + attn_lif
    attn_kernel<<<dim3(NW_, B_, T_), 128>>>(spkf, obuf);
    lif_spk_kernel<<<lifC, 256>>>((const float2*)obuf, (__half2*)aspk, PLANE_C / 2, 0.5f);

    // proj (spike A, 2 passes) -> x1 = x + spikes, + x1 splits
    gemm_mma<1, 4><<<dim3(C_ / 128, M_TOT / 128), 256, SZ1>>>(
        aspk, aspk, ws + WOFF_P, ws + WTOT + WOFF_P,
        pb, ps, pt, pre, C_, C_);
    lif_add_split_kernel<<<lifC, 256>>>((const float2*)pre, (const float2*)x,
        (float2*)x1b, (__half2*)x1s, (__half2*)(x1s + MC), PLANE_C / 2);

    // f1 (float A, 4 passes) -> h spikes
    gemm_mma<2, 3><<<dim3(HD_ / 128, M_TOT / 128), 256, SZ2>>>(
        x1s, x1s + MC, ws + WOFF_F1, ws + WTOT + WOFF_F1,
        f1b, f1s, f1t, pre, HD_, C_);
    lif_spk_kernel<<<lifH, 256>>>((const float2*)pre, (__half2*)hspk, PLANE_H / 2, 1.0f);

    // f2 (spike A, 2 passes) -> out = x1 + spikes
    gemm_mma<1, 4><<<dim3(C_ / 128, M_TOT / 128), 256, SZ1>>>(
        hspk, hspk, ws + WOFF_F2, ws + WTOT + WOFF_F2,
        f2b, f2s, f2t, obuf, C_, HD_);
    lif_add_kernel<<<lifC, 256>>>((const float2*)obuf, (const float2*)x1b,
                                  (float2*)d_out, PLANE_C / 2);
}